// round 2
// baseline (speedup 1.0000x reference)
#include <cuda_runtime.h>
#include <cstdint>

#define T_TOK 8192
#define DIM   1024
#define NE    16
#define TOPK  2
#define INTER 2048
#define NR    (T_TOK * TOPK)   // 16384 token-expert assignments
#define MAX_TILES 160          // sum ceil(n_e/128) <= 144

// ---------------- device scratch (no allocations allowed) ----------------
__device__ int   g_topi[NR];
__device__ float g_topw[NR];
__device__ int   g_cnt[NE];
__device__ int   g_off[NE + 1];
__device__ int   g_pos[NE];
__device__ int   g_tok[NR];     // token id per (expert-sorted) row
__device__ float g_w[NR];       // routing weight per row
__device__ int   g_tm_e[MAX_TILES];
__device__ int   g_tm_m[MAX_TILES];
__device__ int   g_ntiles;
__device__ float g_H[(size_t)(NR + 128) * INTER];  // ~135 MB intermediate

// ---------------- helpers ----------------
__device__ __forceinline__ uint32_t f2tf(float f) {
    uint32_t u;
    asm("cvt.rna.tf32.f32 %0, %1;" : "=r"(u) : "f"(f));
    return u;
}

__device__ __forceinline__ void mma_tf32(float (&c)[4], const uint32_t (&a)[4],
                                         const uint32_t (&b)[2]) {
    asm volatile(
        "mma.sync.aligned.m16n8k8.row.col.f32.tf32.tf32.f32 "
        "{%0,%1,%2,%3}, {%4,%5,%6,%7}, {%8,%9}, {%0,%1,%2,%3};\n"
        : "+f"(c[0]), "+f"(c[1]), "+f"(c[2]), "+f"(c[3])
        : "r"(a[0]), "r"(a[1]), "r"(a[2]), "r"(a[3]), "r"(b[0]), "r"(b[1]));
}

// ---------------- init ----------------
__global__ void init_kernel() {
    int i = threadIdx.x;
    if (i < NE) g_cnt[i] = 0;
}

// ---------------- gate: logits -> top2 (softmax-renorm == softmax over top2) ----
__global__ void gate_kernel(const float* __restrict__ x,
                            const float* __restrict__ Wg,
                            const float* __restrict__ bg) {
    int t   = blockIdx.x;
    int tid = threadIdx.x;         // 256 threads
    int e   = tid & 15;
    int c   = tid >> 4;            // 16 chunks of 64
    const float* xr = x + (size_t)t * DIM;
    float s = 0.f;
    int d0 = c * 64;
#pragma unroll 8
    for (int d = d0; d < d0 + 64; ++d) s += xr[d] * Wg[d * NE + e];

    __shared__ float part[256];
    __shared__ float logits[NE];
    part[tid] = s;
    __syncthreads();
    if (tid < NE) {
        float tot = bg[tid];
#pragma unroll
        for (int cc = 0; cc < 16; ++cc) tot += part[cc * 16 + tid];
        logits[tid] = tot;
    }
    __syncthreads();
    if (tid == 0) {
        int i0 = 0; float m0 = logits[0];
#pragma unroll
        for (int k = 1; k < NE; ++k)
            if (logits[k] > m0) { m0 = logits[k]; i0 = k; }
        int i1 = -1; float m1 = -3.4e38f;
#pragma unroll
        for (int k = 0; k < NE; ++k)
            if (k != i0 && logits[k] > m1) { m1 = logits[k]; i1 = k; }
        float e1 = expf(m1 - m0);
        float inv = 1.f / (1.f + e1);
        g_topi[t * 2]     = i0;  g_topw[t * 2]     = inv;
        g_topi[t * 2 + 1] = i1;  g_topw[t * 2 + 1] = e1 * inv;
        atomicAdd(&g_cnt[i0], 1);
        atomicAdd(&g_cnt[i1], 1);
    }
}

// ---------------- scan + tile map (serial over 16 experts) ----------------
__global__ void scan_kernel() {
    if (threadIdx.x == 0 && blockIdx.x == 0) {
        int off = 0, nt = 0;
        for (int e = 0; e < NE; ++e) {
            g_off[e] = off;
            g_pos[e] = off;
            int ne = g_cnt[e];
            for (int j = 0; j < ne; j += 128) {
                g_tm_e[nt] = e;
                g_tm_m[nt] = off + j;
                ++nt;
            }
            off += ne;
        }
        g_off[NE] = off;
        g_ntiles  = nt;
    }
}

// ---------------- scatter assignments into expert-sorted rows ----------------
__global__ void scatter_kernel() {
    int i = blockIdx.x * 256 + threadIdx.x;
    if (i < NR) {
        int e = g_topi[i];
        int p = atomicAdd(&g_pos[e], 1);
        g_tok[p] = i >> 1;
        g_w[p]   = g_topw[i];
    }
}

// ---------------- GEMM1: H = silu(X@W1+b1) * (X@W3+b3), gathered A ----------
// block tile 128(M) x 64(N) x 32(K), 8 warps (4x2), warp tile 32x32, tf32 MMA
__global__ __launch_bounds__(256) void gemm1_kernel(
    const float* __restrict__ x,
    const float* __restrict__ W1, const float* __restrict__ b1,
    const float* __restrict__ W3, const float* __restrict__ b3) {
    int t = blockIdx.y;
    if (t >= g_ntiles) return;
    int e       = g_tm_e[t];
    int m0      = g_tm_m[t];
    int row_end = g_off[e + 1];
    int n0      = blockIdx.x * 64;
    int tid  = threadIdx.x;
    int lane = tid & 31;
    int wid  = tid >> 5;
    int wm   = wid >> 1;     // 0..3
    int wn   = wid & 1;      // 0..1

    __shared__ uint32_t As[128][33];
    __shared__ uint32_t Bs1[32][68];
    __shared__ uint32_t Bs3[32][68];
    __shared__ int s_tok[128];

    if (tid < 128) {
        int rg = m0 + tid;
        s_tok[tid] = (rg < row_end) ? g_tok[rg] : 0;
    }
    __syncthreads();

    const float* W1e = W1 + (size_t)e * (DIM * INTER);
    const float* W3e = W3 + (size_t)e * (DIM * INTER);

    float acc1[2][4][4], acc3[2][4][4];
#pragma unroll
    for (int mf = 0; mf < 2; ++mf)
#pragma unroll
        for (int nf = 0; nf < 4; ++nf)
#pragma unroll
            for (int i = 0; i < 4; ++i) { acc1[mf][nf][i] = 0.f; acc3[mf][nf][i] = 0.f; }

    // register-prefetch pipeline
    float4 pA[4], pB1[2], pB3[2];
#pragma unroll
    for (int it = 0; it < 4; ++it) {
        int idx = tid + it * 256, r = idx >> 3, q = idx & 7;
        pA[it] = *(const float4*)(x + (size_t)s_tok[r] * DIM + q * 4);
    }
#pragma unroll
    for (int it = 0; it < 2; ++it) {
        int idx = tid + it * 256, kr = idx >> 4, q = idx & 15;
        pB1[it] = *(const float4*)(W1e + (size_t)kr * INTER + n0 + q * 4);
        pB3[it] = *(const float4*)(W3e + (size_t)kr * INTER + n0 + q * 4);
    }

    for (int k0 = 0; k0 < DIM; k0 += 32) {
#pragma unroll
        for (int it = 0; it < 4; ++it) {
            int idx = tid + it * 256, r = idx >> 3, q = idx & 7;
            As[r][q * 4 + 0] = f2tf(pA[it].x);
            As[r][q * 4 + 1] = f2tf(pA[it].y);
            As[r][q * 4 + 2] = f2tf(pA[it].z);
            As[r][q * 4 + 3] = f2tf(pA[it].w);
        }
#pragma unroll
        for (int it = 0; it < 2; ++it) {
            int idx = tid + it * 256, kr = idx >> 4, q = idx & 15;
            Bs1[kr][q * 4 + 0] = f2tf(pB1[it].x);
            Bs1[kr][q * 4 + 1] = f2tf(pB1[it].y);
            Bs1[kr][q * 4 + 2] = f2tf(pB1[it].z);
            Bs1[kr][q * 4 + 3] = f2tf(pB1[it].w);
            Bs3[kr][q * 4 + 0] = f2tf(pB3[it].x);
            Bs3[kr][q * 4 + 1] = f2tf(pB3[it].y);
            Bs3[kr][q * 4 + 2] = f2tf(pB3[it].z);
            Bs3[kr][q * 4 + 3] = f2tf(pB3[it].w);
        }
        __syncthreads();

        int k1 = k0 + 32;
        if (k1 < DIM) {
#pragma unroll
            for (int it = 0; it < 4; ++it) {
                int idx = tid + it * 256, r = idx >> 3, q = idx & 7;
                pA[it] = *(const float4*)(x + (size_t)s_tok[r] * DIM + k1 + q * 4);
            }
#pragma unroll
            for (int it = 0; it < 2; ++it) {
                int idx = tid + it * 256, kr = idx >> 4, q = idx & 15;
                pB1[it] = *(const float4*)(W1e + (size_t)(k1 + kr) * INTER + n0 + q * 4);
                pB3[it] = *(const float4*)(W3e + (size_t)(k1 + kr) * INTER + n0 + q * 4);
            }
        }

#pragma unroll
        for (int kk = 0; kk < 32; kk += 8) {
            uint32_t af[2][4];
            int ar = wm * 32 + (lane >> 2);
            int ac = kk + (lane & 3);
#pragma unroll
            for (int mf = 0; mf < 2; ++mf) {
                af[mf][0] = As[ar + mf * 16][ac];
                af[mf][1] = As[ar + mf * 16 + 8][ac];
                af[mf][2] = As[ar + mf * 16][ac + 4];
                af[mf][3] = As[ar + mf * 16 + 8][ac + 4];
            }
            int bk = kk + (lane & 3);
            int bc = wn * 32 + (lane >> 2);
#pragma unroll
            for (int nf = 0; nf < 4; ++nf) {
                uint32_t b1f[2] = { Bs1[bk][bc + nf * 8], Bs1[bk + 4][bc + nf * 8] };
                uint32_t b3f[2] = { Bs3[bk][bc + nf * 8], Bs3[bk + 4][bc + nf * 8] };
#pragma unroll
                for (int mf = 0; mf < 2; ++mf) {
                    mma_tf32(acc1[mf][nf], af[mf], b1f);
                    mma_tf32(acc3[mf][nf], af[mf], b3f);
                }
            }
        }
        __syncthreads();
    }

    // epilogue: silu(h1 + b1) * (h3 + b3) -> g_H
#pragma unroll
    for (int mf = 0; mf < 2; ++mf)
#pragma unroll
        for (int nf = 0; nf < 4; ++nf)
#pragma unroll
            for (int i = 0; i < 4; ++i) {
                int r  = wm * 32 + mf * 16 + (lane >> 2) + ((i >= 2) ? 8 : 0);
                int cn = wn * 32 + nf * 8 + (lane & 3) * 2 + (i & 1);
                int rg = m0 + r;
                if (rg < row_end) {
                    int ng  = n0 + cn;
                    float a = acc1[mf][nf][i] + b1[e * INTER + ng];
                    float g = a / (1.f + __expf(-a));
                    g_H[(size_t)rg * INTER + ng] =
                        g * (acc3[mf][nf][i] + b3[e * INTER + ng]);
                }
            }
}

// ---------------- GEMM2: y += (H @ W2 + b2) * w, atomic accumulate ----------
__global__ __launch_bounds__(256) void gemm2_kernel(
    const float* __restrict__ W2, const float* __restrict__ b2,
    float* __restrict__ y) {
    int t = blockIdx.y;
    if (t >= g_ntiles) return;
    int e       = g_tm_e[t];
    int m0      = g_tm_m[t];
    int row_end = g_off[e + 1];
    int n0      = blockIdx.x * 64;
    int tid  = threadIdx.x;
    int lane = tid & 31;
    int wid  = tid >> 5;
    int wm   = wid >> 1;
    int wn   = wid & 1;

    __shared__ uint32_t As[128][33];
    __shared__ uint32_t Bs[32][68];

    const float* W2e = W2 + (size_t)e * (INTER * DIM);

    float acc[2][4][4];
#pragma unroll
    for (int mf = 0; mf < 2; ++mf)
#pragma unroll
        for (int nf = 0; nf < 4; ++nf)
#pragma unroll
            for (int i = 0; i < 4; ++i) acc[mf][nf][i] = 0.f;

    float4 pA[4], pB[2];
#pragma unroll
    for (int it = 0; it < 4; ++it) {
        int idx = tid + it * 256, r = idx >> 3, q = idx & 7;
        pA[it] = *(const float4*)(g_H + (size_t)(m0 + r) * INTER + q * 4);
    }
#pragma unroll
    for (int it = 0; it < 2; ++it) {
        int idx = tid + it * 256, kr = idx >> 4, q = idx & 15;
        pB[it] = *(const float4*)(W2e + (size_t)kr * DIM + n0 + q * 4);
    }

    for (int k0 = 0; k0 < INTER; k0 += 32) {
#pragma unroll
        for (int it = 0; it < 4; ++it) {
            int idx = tid + it * 256, r = idx >> 3, q = idx & 7;
            As[r][q * 4 + 0] = f2tf(pA[it].x);
            As[r][q * 4 + 1] = f2tf(pA[it].y);
            As[r][q * 4 + 2] = f2tf(pA[it].z);
            As[r][q * 4 + 3] = f2tf(pA[it].w);
        }
#pragma unroll
        for (int it = 0; it < 2; ++it) {
            int idx = tid + it * 256, kr = idx >> 4, q = idx & 15;
            Bs[kr][q * 4 + 0] = f2tf(pB[it].x);
            Bs[kr][q * 4 + 1] = f2tf(pB[it].y);
            Bs[kr][q * 4 + 2] = f2tf(pB[it].z);
            Bs[kr][q * 4 + 3] = f2tf(pB[it].w);
        }
        __syncthreads();

        int k1 = k0 + 32;
        if (k1 < INTER) {
#pragma unroll
            for (int it = 0; it < 4; ++it) {
                int idx = tid + it * 256, r = idx >> 3, q = idx & 7;
                pA[it] = *(const float4*)(g_H + (size_t)(m0 + r) * INTER + k1 + q * 4);
            }
#pragma unroll
            for (int it = 0; it < 2; ++it) {
                int idx = tid + it * 256, kr = idx >> 4, q = idx & 15;
                pB[it] = *(const float4*)(W2e + (size_t)(k1 + kr) * DIM + n0 + q * 4);
            }
        }

#pragma unroll
        for (int kk = 0; kk < 32; kk += 8) {
            uint32_t af[2][4];
            int ar = wm * 32 + (lane >> 2);
            int ac = kk + (lane & 3);
#pragma unroll
            for (int mf = 0; mf < 2; ++mf) {
                af[mf][0] = As[ar + mf * 16][ac];
                af[mf][1] = As[ar + mf * 16 + 8][ac];
                af[mf][2] = As[ar + mf * 16][ac + 4];
                af[mf][3] = As[ar + mf * 16 + 8][ac + 4];
            }
            int bk = kk + (lane & 3);
            int bc = wn * 32 + (lane >> 2);
#pragma unroll
            for (int nf = 0; nf < 4; ++nf) {
                uint32_t bf[2] = { Bs[bk][bc + nf * 8], Bs[bk + 4][bc + nf * 8] };
#pragma unroll
                for (int mf = 0; mf < 2; ++mf) mma_tf32(acc[mf][nf], af[mf], bf);
            }
        }
        __syncthreads();
    }

    // epilogue: scale by routing weight, atomic accumulate into y
#pragma unroll
    for (int mf = 0; mf < 2; ++mf)
#pragma unroll
        for (int nf = 0; nf < 4; ++nf)
#pragma unroll
            for (int i = 0; i < 4; ++i) {
                int r  = wm * 32 + mf * 16 + (lane >> 2) + ((i >= 2) ? 8 : 0);
                int cn = wn * 32 + nf * 8 + (lane & 3) * 2 + (i & 1);
                int rg = m0 + r;
                if (rg < row_end) {
                    int tok = g_tok[rg];
                    float w = g_w[rg];
                    int ng  = n0 + cn;
                    float v = (acc[mf][nf][i] + b2[e * DIM + ng]) * w;
                    atomicAdd(&y[(size_t)tok * DIM + ng], v);
                }
            }
}

// ---------------- launch ----------------
extern "C" void kernel_launch(void* const* d_in, const int* in_sizes, int n_in,
                              void* d_out, int out_size) {
    (void)in_sizes; (void)n_in; (void)out_size;
    const float* x  = (const float*)d_in[0];
    const float* Wg = (const float*)d_in[1];
    const float* bg = (const float*)d_in[2];
    const float* W1 = (const float*)d_in[3];
    const float* b1 = (const float*)d_in[4];
    const float* W2 = (const float*)d_in[5];
    const float* b2 = (const float*)d_in[6];
    const float* W3 = (const float*)d_in[7];
    const float* b3 = (const float*)d_in[8];
    float* y = (float*)d_out;

    cudaMemsetAsync(y, 0, (size_t)T_TOK * DIM * sizeof(float), 0);
    init_kernel<<<1, 32>>>();
    gate_kernel<<<T_TOK, 256>>>(x, Wg, bg);
    scan_kernel<<<1, 32>>>();
    scatter_kernel<<<NR / 256, 256>>>();
    gemm1_kernel<<<dim3(INTER / 64, 144), 256>>>(x, W1, b1, W3, b3);
    gemm2_kernel<<<dim3(DIM / 64, 144), 256>>>(W2, b2, y);
}

// round 6
// speedup vs baseline: 2.8944x; 2.8944x over previous
#include <cuda_runtime.h>
#include <cuda_fp16.h>
#include <cstdint>

#define T_TOK 8192
#define DIM   1024
#define NE    16
#define INTER 2048
#define NR    (T_TOK * 2)
#define MAX_TILES 160

// ---------------- device scratch ----------------
__device__ int    g_topi[NR];
__device__ float  g_topw[NR];
__device__ int    g_cnt[NE];
__device__ int    g_off[NE + 1];
__device__ int    g_pos[NE];
__device__ int    g_tok[NR];
__device__ float  g_w[NR];
__device__ int    g_tm_e[MAX_TILES];
__device__ int    g_tm_m[MAX_TILES];
__device__ int    g_ntiles;
__device__ __half g_xh[(size_t)T_TOK * DIM];
__device__ __half g_W1h[(size_t)NE * DIM * INTER];   // [e][k][n] as in source
__device__ __half g_W3h[(size_t)NE * DIM * INTER];
__device__ __half g_W2h[(size_t)NE * INTER * DIM];
__device__ __half g_Hh[(size_t)(NR + 128) * INTER];  // zero-init; padding rows stay 0

// ---------------- helpers ----------------
__device__ __forceinline__ uint32_t smem_u32(const void* p) {
    uint32_t a;
    asm("{ .reg .u64 t; cvta.to.shared.u64 t, %1; cvt.u32.u64 %0, t; }" : "=r"(a) : "l"(p));
    return a;
}

__device__ __forceinline__ void mma_f16(float* c, const uint32_t* a, const uint32_t* b) {
    asm volatile(
        "mma.sync.aligned.m16n8k16.row.col.f32.f16.f16.f32 "
        "{%0,%1,%2,%3}, {%4,%5,%6,%7}, {%8,%9}, {%0,%1,%2,%3};\n"
        : "+f"(c[0]), "+f"(c[1]), "+f"(c[2]), "+f"(c[3])
        : "r"(a[0]), "r"(a[1]), "r"(a[2]), "r"(a[3]), "r"(b[0]), "r"(b[1]));
}

#define LDSM_X4(r, addr) \
    asm volatile("ldmatrix.sync.aligned.m8n8.x4.shared.b16 {%0,%1,%2,%3}, [%4];" \
        : "=r"((r)[0]), "=r"((r)[1]), "=r"((r)[2]), "=r"((r)[3]) : "r"(addr))
#define LDSM_X4_T(r, addr) \
    asm volatile("ldmatrix.sync.aligned.m8n8.x4.trans.shared.b16 {%0,%1,%2,%3}, [%4];" \
        : "=r"((r)[0]), "=r"((r)[1]), "=r"((r)[2]), "=r"((r)[3]) : "r"(addr))

#define CP_ASYNC16(dst, src) \
    asm volatile("cp.async.cg.shared.global [%0], [%1], 16;\n" :: "r"(dst), "l"(src) : "memory")
#define CP_COMMIT() asm volatile("cp.async.commit_group;\n" ::: "memory")
#define CP_WAIT2()  asm volatile("cp.async.wait_group 2;\n" ::: "memory")

// strides (bytes): A tile 128x32 fp16 rows padded 64->80B; B tile 32x128 fp16 rows 256->272B
#define A_STRIDE 80
#define B_STRIDE 272
#define S1_STAGE (128 * A_STRIDE + 2 * 32 * B_STRIDE)   // 27648
#define S2_STAGE (128 * A_STRIDE + 32 * B_STRIDE)        // 18944

// ---------------- routing ----------------
__global__ void init_kernel() {
    int i = threadIdx.x;
    if (i < NE) g_cnt[i] = 0;
}

__global__ void gate_kernel(const float* __restrict__ x,
                            const float* __restrict__ Wg,
                            const float* __restrict__ bg) {
    int t = blockIdx.x, tid = threadIdx.x;
    int e = tid & 15, c = tid >> 4;
    const float* xr = x + (size_t)t * DIM;
    float s = 0.f;
    int d0 = c * 64;
#pragma unroll 8
    for (int d = d0; d < d0 + 64; ++d) s += xr[d] * Wg[d * NE + e];
    __shared__ float part[256];
    __shared__ float logits[NE];
    part[tid] = s;
    __syncthreads();
    if (tid < NE) {
        float tot = bg[tid];
#pragma unroll
        for (int cc = 0; cc < 16; ++cc) tot += part[cc * 16 + tid];
        logits[tid] = tot;
    }
    __syncthreads();
    if (tid == 0) {
        int i0 = 0; float m0 = logits[0];
#pragma unroll
        for (int k = 1; k < NE; ++k)
            if (logits[k] > m0) { m0 = logits[k]; i0 = k; }
        int i1 = -1; float m1 = -3.4e38f;
#pragma unroll
        for (int k = 0; k < NE; ++k)
            if (k != i0 && logits[k] > m1) { m1 = logits[k]; i1 = k; }
        float e1 = expf(m1 - m0);
        float inv = 1.f / (1.f + e1);
        g_topi[t * 2]     = i0;  g_topw[t * 2]     = inv;
        g_topi[t * 2 + 1] = i1;  g_topw[t * 2 + 1] = e1 * inv;
        atomicAdd(&g_cnt[i0], 1);
        atomicAdd(&g_cnt[i1], 1);
    }
}

__global__ void scan_kernel() {
    if (threadIdx.x == 0 && blockIdx.x == 0) {
        int off = 0, nt = 0;
        for (int e = 0; e < NE; ++e) {
            g_off[e] = off; g_pos[e] = off;
            int ne = g_cnt[e];
            for (int j = 0; j < ne; j += 128) { g_tm_e[nt] = e; g_tm_m[nt] = off + j; ++nt; }
            off += ne;
        }
        g_off[NE] = off;
        g_ntiles  = nt;
    }
}

__global__ void scatter_kernel() {
    int i = blockIdx.x * 256 + threadIdx.x;
    if (i < NR) {
        int e = g_topi[i];
        int p = atomicAdd(&g_pos[e], 1);
        g_tok[p] = i >> 1;
        g_w[p]   = g_topw[i];
    }
}

// ---------------- fp32 -> fp16 convert (coalesced, 4 elems/thread) ----------------
__global__ void cvt16_kernel(const float4* __restrict__ in, __half2* __restrict__ out) {
    size_t i = (size_t)blockIdx.x * blockDim.x + threadIdx.x;
    float4 v = in[i];
    out[2 * i]     = __floats2half2_rn(v.x, v.y);
    out[2 * i + 1] = __floats2half2_rn(v.z, v.w);
}

// ---------------- GEMM1: H = silu(X@W1+b1) * (X@W3+b3) ----------------
// block 128M x 128N x 32K, 8 warps (2M x 4N), warp tile 64x32, m16n8k16 fp16 MMA
__global__ __launch_bounds__(256, 1) void gemm1_hm(const float* __restrict__ b1,
                                                   const float* __restrict__ b3) {
    int t = blockIdx.y;
    if (t >= g_ntiles) return;
    int e = g_tm_e[t], m0 = g_tm_m[t], row_end = g_off[e + 1];
    int n0 = blockIdx.x * 128;
    int tid = threadIdx.x, lane = tid & 31, wid = tid >> 5;
    int wm = wid >> 2, wn = wid & 3;

    extern __shared__ char sm[];
    uint32_t sb = (smem_u32(sm) + 127) & ~127u;

    __shared__ int s_tok[128];
    if (tid < 128) {
        int rg = m0 + tid;
        s_tok[tid] = (rg < row_end) ? g_tok[rg] : 0;
    }
    __syncthreads();

    const __half* W1e = g_W1h + (size_t)e * DIM * INTER;
    const __half* W3e = g_W3h + (size_t)e * DIM * INTER;

    // per-thread fill descriptors (2 x A chunk, 2 x B1, 2 x B3 per stage)
    const __half* srcA[2]; const __half* srcB1[2]; const __half* srcB3[2];
    uint32_t dA[2], dB[2];
#pragma unroll
    for (int it = 0; it < 2; ++it) {
        int idx = tid + it * 256;
        int rowA = idx >> 2, kcA = idx & 3;
        srcA[it] = g_xh + (size_t)s_tok[rowA] * DIM + kcA * 8;
        dA[it]   = rowA * A_STRIDE + kcA * 16;
        int krB = idx >> 4, ncB = idx & 15;
        srcB1[it] = W1e + (size_t)krB * INTER + n0 + ncB * 8;
        srcB3[it] = W3e + (size_t)krB * INTER + n0 + ncB * 8;
        dB[it]    = krB * B_STRIDE + ncB * 16;
    }

    float acc1[4][4][4], acc3[4][4][4];
#pragma unroll
    for (int mi = 0; mi < 4; ++mi)
#pragma unroll
        for (int ni = 0; ni < 4; ++ni)
#pragma unroll
            for (int q = 0; q < 4; ++q) { acc1[mi][ni][q] = 0.f; acc3[mi][ni][q] = 0.f; }

    auto load_chunk = [&](int c) {
        if (c < 32) {
            uint32_t st = sb + (c % 3) * S1_STAGE;
            uint32_t sa = st, sb1 = st + 128 * A_STRIDE, sb3 = sb1 + 32 * B_STRIDE;
            int ko = c * 32;
#pragma unroll
            for (int it = 0; it < 2; ++it) CP_ASYNC16(sa + dA[it], srcA[it] + ko);
#pragma unroll
            for (int it = 0; it < 2; ++it) CP_ASYNC16(sb1 + dB[it], srcB1[it] + (size_t)ko * INTER);
#pragma unroll
            for (int it = 0; it < 2; ++it) CP_ASYNC16(sb3 + dB[it], srcB3[it] + (size_t)ko * INTER);
        }
        CP_COMMIT();
    };

    load_chunk(0);
    load_chunk(1);

    int lrow = lane & 15, lcol = (lane >> 4) << 3;

    for (int j = 0; j < 32; ++j) {
        load_chunk(j + 2);
        CP_WAIT2();
        __syncthreads();
        uint32_t st = sb + (j % 3) * S1_STAGE;
        uint32_t sa = st, sb1 = st + 128 * A_STRIDE, sb3 = sb1 + 32 * B_STRIDE;
#pragma unroll
        for (int ks = 0; ks < 2; ++ks) {
            uint32_t af[4][4];
#pragma unroll
            for (int mi = 0; mi < 4; ++mi) {
                uint32_t addr = sa + (wm * 64 + mi * 16 + lrow) * A_STRIDE + (ks * 16 + lcol) * 2;
                LDSM_X4(af[mi], addr);
            }
            uint32_t bf1[2][4], bf3[2][4];
#pragma unroll
            for (int nh = 0; nh < 2; ++nh) {
                uint32_t col2 = (wn * 32 + nh * 16 + lcol) * 2;
                uint32_t rowo = (ks * 16 + lrow) * B_STRIDE;
                LDSM_X4_T(bf1[nh], sb1 + rowo + col2);
                LDSM_X4_T(bf3[nh], sb3 + rowo + col2);
            }
#pragma unroll
            for (int mi = 0; mi < 4; ++mi)
#pragma unroll
                for (int ni = 0; ni < 4; ++ni) {
                    mma_f16(acc1[mi][ni], af[mi], &bf1[ni >> 1][(ni & 1) * 2]);
                    mma_f16(acc3[mi][ni], af[mi], &bf3[ni >> 1][(ni & 1) * 2]);
                }
        }
        __syncthreads();
    }

    // epilogue: silu(h1+b1)*(h3+b3) -> g_Hh (fp16)
    int g = lane >> 2, tg = lane & 3;
#pragma unroll
    for (int mi = 0; mi < 4; ++mi)
#pragma unroll
        for (int rr = 0; rr < 2; ++rr) {
            int rg = m0 + wm * 64 + mi * 16 + g + rr * 8;
            if (rg < row_end) {
                size_t hrow = (size_t)rg * INTER;
#pragma unroll
                for (int ni = 0; ni < 4; ++ni) {
                    int n = n0 + wn * 32 + ni * 8 + tg * 2;
                    float a0 = acc1[mi][ni][rr * 2]     + b1[e * INTER + n];
                    float a1 = acc1[mi][ni][rr * 2 + 1] + b1[e * INTER + n + 1];
                    float g0 = a0 / (1.f + __expf(-a0));
                    float g1 = a1 / (1.f + __expf(-a1));
                    float h0 = g0 * (acc3[mi][ni][rr * 2]     + b3[e * INTER + n]);
                    float h1 = g1 * (acc3[mi][ni][rr * 2 + 1] + b3[e * INTER + n + 1]);
                    *(__half2*)(g_Hh + hrow + n) = __floats2half2_rn(h0, h1);
                }
            }
        }
}

// ---------------- GEMM2: y += (H @ W2 + b2) * w ----------------
__global__ __launch_bounds__(256, 2) void gemm2_hm(const float* __restrict__ b2,
                                                   float* __restrict__ y) {
    int t = blockIdx.y;
    if (t >= g_ntiles) return;
    int e = g_tm_e[t], m0 = g_tm_m[t], row_end = g_off[e + 1];
    int n0 = blockIdx.x * 128;
    int tid = threadIdx.x, lane = tid & 31, wid = tid >> 5;
    int wm = wid >> 2, wn = wid & 3;

    extern __shared__ char sm[];
    uint32_t sb = (smem_u32(sm) + 127) & ~127u;

    const __half* W2e = g_W2h + (size_t)e * INTER * DIM;

    const __half* srcA[2]; const __half* srcB[2];
    uint32_t dA[2], dB[2];
#pragma unroll
    for (int it = 0; it < 2; ++it) {
        int idx = tid + it * 256;
        int rowA = idx >> 2, kcA = idx & 3;
        srcA[it] = g_Hh + (size_t)(m0 + rowA) * INTER + kcA * 8;
        dA[it]   = rowA * A_STRIDE + kcA * 16;
        int krB = idx >> 4, ncB = idx & 15;
        srcB[it] = W2e + (size_t)krB * DIM + n0 + ncB * 8;
        dB[it]   = krB * B_STRIDE + ncB * 16;
    }

    float acc[4][4][4];
#pragma unroll
    for (int mi = 0; mi < 4; ++mi)
#pragma unroll
        for (int ni = 0; ni < 4; ++ni)
#pragma unroll
            for (int q = 0; q < 4; ++q) acc[mi][ni][q] = 0.f;

    auto load_chunk = [&](int c) {
        if (c < 64) {
            uint32_t st = sb + (c % 3) * S2_STAGE;
            uint32_t sa = st, sbB = st + 128 * A_STRIDE;
            int ko = c * 32;
#pragma unroll
            for (int it = 0; it < 2; ++it) CP_ASYNC16(sa + dA[it], srcA[it] + ko);
#pragma unroll
            for (int it = 0; it < 2; ++it) CP_ASYNC16(sbB + dB[it], srcB[it] + (size_t)ko * DIM);
        }
        CP_COMMIT();
    };

    load_chunk(0);
    load_chunk(1);

    int lrow = lane & 15, lcol = (lane >> 4) << 3;

    for (int j = 0; j < 64; ++j) {
        load_chunk(j + 2);
        CP_WAIT2();
        __syncthreads();
        uint32_t st = sb + (j % 3) * S2_STAGE;
        uint32_t sa = st, sbB = st + 128 * A_STRIDE;
#pragma unroll
        for (int ks = 0; ks < 2; ++ks) {
            uint32_t af[4][4];
#pragma unroll
            for (int mi = 0; mi < 4; ++mi) {
                uint32_t addr = sa + (wm * 64 + mi * 16 + lrow) * A_STRIDE + (ks * 16 + lcol) * 2;
                LDSM_X4(af[mi], addr);
            }
            uint32_t bf[2][4];
#pragma unroll
            for (int nh = 0; nh < 2; ++nh) {
                uint32_t col2 = (wn * 32 + nh * 16 + lcol) * 2;
                LDSM_X4_T(bf[nh], sbB + (ks * 16 + lrow) * B_STRIDE + col2);
            }
#pragma unroll
            for (int mi = 0; mi < 4; ++mi)
#pragma unroll
                for (int ni = 0; ni < 4; ++ni)
                    mma_f16(acc[mi][ni], af[mi], &bf[ni >> 1][(ni & 1) * 2]);
        }
        __syncthreads();
    }

    int g = lane >> 2, tg = lane & 3;
#pragma unroll
    for (int mi = 0; mi < 4; ++mi)
#pragma unroll
        for (int rr = 0; rr < 2; ++rr) {
            int rg = m0 + wm * 64 + mi * 16 + g + rr * 8;
            if (rg < row_end) {
                int tok = g_tok[rg];
                float wgt = g_w[rg];
                float* yrow = y + (size_t)tok * DIM;
#pragma unroll
                for (int ni = 0; ni < 4; ++ni) {
                    int n = n0 + wn * 32 + ni * 8 + tg * 2;
                    float v0 = (acc[mi][ni][rr * 2]     + b2[e * DIM + n])     * wgt;
                    float v1 = (acc[mi][ni][rr * 2 + 1] + b2[e * DIM + n + 1]) * wgt;
                    atomicAdd(yrow + n, v0);
                    atomicAdd(yrow + n + 1, v1);
                }
            }
        }
}

// ---------------- launch ----------------
extern "C" void kernel_launch(void* const* d_in, const int* in_sizes, int n_in,
                              void* d_out, int out_size) {
    (void)in_sizes; (void)n_in; (void)out_size;
    const float* x  = (const float*)d_in[0];
    const float* Wg = (const float*)d_in[1];
    const float* bg = (const float*)d_in[2];
    const float* W1 = (const float*)d_in[3];
    const float* b1 = (const float*)d_in[4];
    const float* W2 = (const float*)d_in[5];
    const float* b2 = (const float*)d_in[6];
    const float* W3 = (const float*)d_in[7];
    const float* b3 = (const float*)d_in[8];
    float* y = (float*)d_out;

    const int G1_SMEM = 128 + 3 * S1_STAGE;   // ~83 KB
    const int G2_SMEM = 128 + 3 * S2_STAGE;   // ~57 KB
    cudaFuncSetAttribute(gemm1_hm, cudaFuncAttributeMaxDynamicSharedMemorySize, G1_SMEM);
    cudaFuncSetAttribute(gemm2_hm, cudaFuncAttributeMaxDynamicSharedMemorySize, G2_SMEM);

    cudaMemsetAsync(y, 0, (size_t)T_TOK * DIM * sizeof(float), 0);
    init_kernel<<<1, 32>>>();
    gate_kernel<<<T_TOK, 256>>>(x, Wg, bg);
    scan_kernel<<<1, 32>>>();
    scatter_kernel<<<NR / 256, 256>>>();

    // fp32 -> fp16 conversions
    __half* xh;  cudaGetSymbolAddress((void**)&xh,  g_xh);
    __half* w1h; cudaGetSymbolAddress((void**)&w1h, g_W1h);
    __half* w3h; cudaGetSymbolAddress((void**)&w3h, g_W3h);
    __half* w2h; cudaGetSymbolAddress((void**)&w2h, g_W2h);
    cvt16_kernel<<<(T_TOK * DIM / 4) / 256, 256>>>((const float4*)x, (__half2*)xh);
    cvt16_kernel<<<(NE * DIM * INTER / 4) / 256, 256>>>((const float4*)W1, (__half2*)w1h);
    cvt16_kernel<<<(NE * DIM * INTER / 4) / 256, 256>>>((const float4*)W3, (__half2*)w3h);
    cvt16_kernel<<<(NE * INTER * DIM / 4) / 256, 256>>>((const float4*)W2, (__half2*)w2h);

    gemm1_hm<<<dim3(INTER / 128, 144), 256, G1_SMEM>>>(b1, b3);
    gemm2_hm<<<dim3(DIM / 128, 144), 256, G2_SMEM>>>(b2, y);
}

// round 7
// speedup vs baseline: 3.1894x; 1.1019x over previous
#include <cuda_runtime.h>
#include <cuda_fp16.h>
#include <cstdint>

#define T_TOK 8192
#define DIM   1024
#define NE    16
#define INTER 2048
#define NR    (T_TOK * 2)
#define MAX_TILES 160

// ---------------- device scratch ----------------
__device__ int    g_topi[NR];
__device__ float  g_topw[NR];
__device__ int    g_cnt[NE];
__device__ int    g_off[NE + 1];
__device__ int    g_pos[NE];
__device__ int    g_tok[NR];
__device__ float  g_w[NR];
__device__ int    g_tm_e[MAX_TILES];
__device__ int    g_tm_m[MAX_TILES];
__device__ int    g_ntiles;
__device__ __half g_xh[(size_t)T_TOK * DIM];
__device__ __half g_W1h[(size_t)NE * DIM * INTER];   // [e][k][n] as in source
__device__ __half g_W3h[(size_t)NE * DIM * INTER];
__device__ __half g_W2h[(size_t)NE * INTER * DIM];
__device__ __half g_Hh[(size_t)(NR + 128) * INTER];  // zero-init; padding rows stay 0

// ---------------- helpers ----------------
__device__ __forceinline__ uint32_t smem_u32(const void* p) {
    uint32_t a;
    asm("{ .reg .u64 t; cvta.to.shared.u64 t, %1; cvt.u32.u64 %0, t; }" : "=r"(a) : "l"(p));
    return a;
}

__device__ __forceinline__ void mma_f16(float* c, const uint32_t* a, const uint32_t* b) {
    asm volatile(
        "mma.sync.aligned.m16n8k16.row.col.f32.f16.f16.f32 "
        "{%0,%1,%2,%3}, {%4,%5,%6,%7}, {%8,%9}, {%0,%1,%2,%3};\n"
        : "+f"(c[0]), "+f"(c[1]), "+f"(c[2]), "+f"(c[3])
        : "r"(a[0]), "r"(a[1]), "r"(a[2]), "r"(a[3]), "r"(b[0]), "r"(b[1]));
}

#define LDSM_X4(r, addr) \
    asm volatile("ldmatrix.sync.aligned.m8n8.x4.shared.b16 {%0,%1,%2,%3}, [%4];" \
        : "=r"((r)[0]), "=r"((r)[1]), "=r"((r)[2]), "=r"((r)[3]) : "r"(addr))
#define LDSM_X4_T(r, addr) \
    asm volatile("ldmatrix.sync.aligned.m8n8.x4.trans.shared.b16 {%0,%1,%2,%3}, [%4];" \
        : "=r"((r)[0]), "=r"((r)[1]), "=r"((r)[2]), "=r"((r)[3]) : "r"(addr))

#define CP_ASYNC16(dst, src) \
    asm volatile("cp.async.cg.shared.global [%0], [%1], 16;\n" :: "r"(dst), "l"(src) : "memory")
#define CP_COMMIT() asm volatile("cp.async.commit_group;\n" ::: "memory")
#define CP_WAIT3()  asm volatile("cp.async.wait_group 3;\n" ::: "memory")

// strides (bytes): A tile 128x32 fp16 rows padded 64->80B; B tile 32x128 fp16 rows 256->272B
#define A_STRIDE 80
#define B_STRIDE 272
#define S1_STAGE (128 * A_STRIDE + 2 * 32 * B_STRIDE)   // 27648
#define S2_STAGE (128 * A_STRIDE + 32 * B_STRIDE)        // 18944
#define NSTAGE 5

// ---------------- routing ----------------
__global__ void init_kernel() {
    int i = threadIdx.x;
    if (i < NE) g_cnt[i] = 0;
}

// gate + zero y rows (replaces cudaMemset)
__global__ void gate_kernel(const float* __restrict__ x,
                            const float* __restrict__ Wg,
                            const float* __restrict__ bg,
                            float4* __restrict__ y4) {
    int t = blockIdx.x, tid = threadIdx.x;
    y4[(size_t)t * 256 + tid] = make_float4(0.f, 0.f, 0.f, 0.f);
    int e = tid & 15, c = tid >> 4;
    const float* xr = x + (size_t)t * DIM;
    float s = 0.f;
    int d0 = c * 64;
#pragma unroll 8
    for (int d = d0; d < d0 + 64; ++d) s += xr[d] * Wg[d * NE + e];
    __shared__ float part[256];
    __shared__ float logits[NE];
    part[tid] = s;
    __syncthreads();
    if (tid < NE) {
        float tot = bg[tid];
#pragma unroll
        for (int cc = 0; cc < 16; ++cc) tot += part[cc * 16 + tid];
        logits[tid] = tot;
    }
    __syncthreads();
    if (tid == 0) {
        int i0 = 0; float m0 = logits[0];
#pragma unroll
        for (int k = 1; k < NE; ++k)
            if (logits[k] > m0) { m0 = logits[k]; i0 = k; }
        int i1 = -1; float m1 = -3.4e38f;
#pragma unroll
        for (int k = 0; k < NE; ++k)
            if (k != i0 && logits[k] > m1) { m1 = logits[k]; i1 = k; }
        float e1 = expf(m1 - m0);
        float inv = 1.f / (1.f + e1);
        g_topi[t * 2]     = i0;  g_topw[t * 2]     = inv;
        g_topi[t * 2 + 1] = i1;  g_topw[t * 2 + 1] = e1 * inv;
        atomicAdd(&g_cnt[i0], 1);
        atomicAdd(&g_cnt[i1], 1);
    }
}

__global__ void scan_kernel() {
    if (threadIdx.x == 0 && blockIdx.x == 0) {
        int off = 0, nt = 0;
        for (int e = 0; e < NE; ++e) {
            g_off[e] = off; g_pos[e] = off;
            int ne = g_cnt[e];
            for (int j = 0; j < ne; j += 128) { g_tm_e[nt] = e; g_tm_m[nt] = off + j; ++nt; }
            off += ne;
        }
        g_off[NE] = off;
        g_ntiles  = nt;
    }
}

__global__ void scatter_kernel() {
    int i = blockIdx.x * 256 + threadIdx.x;
    if (i < NR) {
        int e = g_topi[i];
        int p = atomicAdd(&g_pos[e], 1);
        g_tok[p] = i >> 1;
        g_w[p]   = g_topw[i];
    }
}

// ---------------- single merged fp32 -> fp16 convert ----------------
#define X4F ((size_t)T_TOK * DIM / 4)            // 2,097,152
#define W4F ((size_t)NE * DIM * INTER / 4)       // 8,388,608
__global__ void cvt_all_kernel(const float4* __restrict__ x,
                               const float4* __restrict__ W1,
                               const float4* __restrict__ W3,
                               const float4* __restrict__ W2) {
    size_t i = (size_t)blockIdx.x * blockDim.x + threadIdx.x;
    const float4* src; __half2* dst; size_t o;
    if (i < X4F)                { src = x;  o = i;                 dst = (__half2*)g_xh; }
    else if (i < X4F + W4F)     { src = W1; o = i - X4F;           dst = (__half2*)g_W1h; }
    else if (i < X4F + 2 * W4F) { src = W3; o = i - X4F - W4F;     dst = (__half2*)g_W3h; }
    else                        { src = W2; o = i - X4F - 2 * W4F; dst = (__half2*)g_W2h; }
    float4 v = src[o];
    dst[2 * o]     = __floats2half2_rn(v.x, v.y);
    dst[2 * o + 1] = __floats2half2_rn(v.z, v.w);
}

// ---------------- GEMM1: H = silu(X@W1+b1) * (X@W3+b3) ----------------
// block 128M x 128N x 32K, 8 warps (2M x 4N), warp tile 64x32, m16n8k16 fp16 MMA
// 5-stage cp.async pipeline, prefetch distance 3, single barrier per chunk.
__global__ __launch_bounds__(256, 1) void gemm1_hm(const float* __restrict__ b1,
                                                   const float* __restrict__ b3) {
    int t = blockIdx.y;
    if (t >= g_ntiles) return;
    int e = g_tm_e[t], m0 = g_tm_m[t], row_end = g_off[e + 1];
    int n0 = blockIdx.x * 128;
    int tid = threadIdx.x, lane = tid & 31, wid = tid >> 5;
    int wm = wid >> 2, wn = wid & 3;

    extern __shared__ char sm[];
    uint32_t sb = (smem_u32(sm) + 127) & ~127u;

    __shared__ int s_tok[128];
    if (tid < 128) {
        int rg = m0 + tid;
        s_tok[tid] = (rg < row_end) ? g_tok[rg] : 0;
    }
    __syncthreads();

    const __half* W1e = g_W1h + (size_t)e * DIM * INTER;
    const __half* W3e = g_W3h + (size_t)e * DIM * INTER;

    const __half* srcA[2]; const __half* srcB1[2]; const __half* srcB3[2];
    uint32_t dA[2], dB[2];
#pragma unroll
    for (int it = 0; it < 2; ++it) {
        int idx = tid + it * 256;
        int rowA = idx >> 2, kcA = idx & 3;
        srcA[it] = g_xh + (size_t)s_tok[rowA] * DIM + kcA * 8;
        dA[it]   = rowA * A_STRIDE + kcA * 16;
        int krB = idx >> 4, ncB = idx & 15;
        srcB1[it] = W1e + (size_t)krB * INTER + n0 + ncB * 8;
        srcB3[it] = W3e + (size_t)krB * INTER + n0 + ncB * 8;
        dB[it]    = krB * B_STRIDE + ncB * 16;
    }

    float acc1[4][4][4], acc3[4][4][4];
#pragma unroll
    for (int mi = 0; mi < 4; ++mi)
#pragma unroll
        for (int ni = 0; ni < 4; ++ni)
#pragma unroll
            for (int q = 0; q < 4; ++q) { acc1[mi][ni][q] = 0.f; acc3[mi][ni][q] = 0.f; }

    auto load_chunk = [&](int c) {
        if (c < 32) {
            uint32_t st = sb + (c % NSTAGE) * S1_STAGE;
            uint32_t sa = st, sb1 = st + 128 * A_STRIDE, sb3 = sb1 + 32 * B_STRIDE;
            int ko = c * 32;
#pragma unroll
            for (int it = 0; it < 2; ++it) CP_ASYNC16(sa + dA[it], srcA[it] + ko);
#pragma unroll
            for (int it = 0; it < 2; ++it) CP_ASYNC16(sb1 + dB[it], srcB1[it] + (size_t)ko * INTER);
#pragma unroll
            for (int it = 0; it < 2; ++it) CP_ASYNC16(sb3 + dB[it], srcB3[it] + (size_t)ko * INTER);
        }
        CP_COMMIT();
    };

    load_chunk(0);
    load_chunk(1);
    load_chunk(2);

    int lrow = lane & 15, lcol = (lane >> 4) << 3;

    for (int j = 0; j < 32; ++j) {
        load_chunk(j + 3);
        CP_WAIT3();            // chunk j resident (3 newer groups may be in flight)
        __syncthreads();       // single barrier per chunk
        uint32_t st = sb + (j % NSTAGE) * S1_STAGE;
        uint32_t sa = st, sb1 = st + 128 * A_STRIDE, sb3 = sb1 + 32 * B_STRIDE;
#pragma unroll
        for (int ks = 0; ks < 2; ++ks) {
            uint32_t af[4][4];
#pragma unroll
            for (int mi = 0; mi < 4; ++mi) {
                uint32_t addr = sa + (wm * 64 + mi * 16 + lrow) * A_STRIDE + (ks * 16 + lcol) * 2;
                LDSM_X4(af[mi], addr);
            }
            uint32_t bf1[2][4], bf3[2][4];
#pragma unroll
            for (int nh = 0; nh < 2; ++nh) {
                uint32_t col2 = (wn * 32 + nh * 16 + lcol) * 2;
                uint32_t rowo = (ks * 16 + lrow) * B_STRIDE;
                LDSM_X4_T(bf1[nh], sb1 + rowo + col2);
                LDSM_X4_T(bf3[nh], sb3 + rowo + col2);
            }
#pragma unroll
            for (int mi = 0; mi < 4; ++mi)
#pragma unroll
                for (int ni = 0; ni < 4; ++ni) {
                    mma_f16(acc1[mi][ni], af[mi], &bf1[ni >> 1][(ni & 1) * 2]);
                    mma_f16(acc3[mi][ni], af[mi], &bf3[ni >> 1][(ni & 1) * 2]);
                }
        }
    }

    // epilogue: silu(h1+b1)*(h3+b3) -> g_Hh (fp16)
    int g = lane >> 2, tg = lane & 3;
#pragma unroll
    for (int mi = 0; mi < 4; ++mi)
#pragma unroll
        for (int rr = 0; rr < 2; ++rr) {
            int rg = m0 + wm * 64 + mi * 16 + g + rr * 8;
            if (rg < row_end) {
                size_t hrow = (size_t)rg * INTER;
#pragma unroll
                for (int ni = 0; ni < 4; ++ni) {
                    int n = n0 + wn * 32 + ni * 8 + tg * 2;
                    float a0 = acc1[mi][ni][rr * 2]     + b1[e * INTER + n];
                    float a1 = acc1[mi][ni][rr * 2 + 1] + b1[e * INTER + n + 1];
                    float g0 = a0 / (1.f + __expf(-a0));
                    float g1 = a1 / (1.f + __expf(-a1));
                    float h0 = g0 * (acc3[mi][ni][rr * 2]     + b3[e * INTER + n]);
                    float h1 = g1 * (acc3[mi][ni][rr * 2 + 1] + b3[e * INTER + n + 1]);
                    *(__half2*)(g_Hh + hrow + n) = __floats2half2_rn(h0, h1);
                }
            }
        }
}

// ---------------- GEMM2: y += (H @ W2 + b2) * w ----------------
__global__ __launch_bounds__(256, 2) void gemm2_hm(const float* __restrict__ b2,
                                                   float* __restrict__ y) {
    int t = blockIdx.y;
    if (t >= g_ntiles) return;
    int e = g_tm_e[t], m0 = g_tm_m[t], row_end = g_off[e + 1];
    int n0 = blockIdx.x * 128;
    int tid = threadIdx.x, lane = tid & 31, wid = tid >> 5;
    int wm = wid >> 2, wn = wid & 3;

    extern __shared__ char sm[];
    uint32_t sb = (smem_u32(sm) + 127) & ~127u;

    const __half* W2e = g_W2h + (size_t)e * INTER * DIM;

    const __half* srcA[2]; const __half* srcB[2];
    uint32_t dA[2], dB[2];
#pragma unroll
    for (int it = 0; it < 2; ++it) {
        int idx = tid + it * 256;
        int rowA = idx >> 2, kcA = idx & 3;
        srcA[it] = g_Hh + (size_t)(m0 + rowA) * INTER + kcA * 8;
        dA[it]   = rowA * A_STRIDE + kcA * 16;
        int krB = idx >> 4, ncB = idx & 15;
        srcB[it] = W2e + (size_t)krB * DIM + n0 + ncB * 8;
        dB[it]   = krB * B_STRIDE + ncB * 16;
    }

    float acc[4][4][4];
#pragma unroll
    for (int mi = 0; mi < 4; ++mi)
#pragma unroll
        for (int ni = 0; ni < 4; ++ni)
#pragma unroll
            for (int q = 0; q < 4; ++q) acc[mi][ni][q] = 0.f;

    auto load_chunk = [&](int c) {
        if (c < 64) {
            uint32_t st = sb + (c % NSTAGE) * S2_STAGE;
            uint32_t sa = st, sbB = st + 128 * A_STRIDE;
            int ko = c * 32;
#pragma unroll
            for (int it = 0; it < 2; ++it) CP_ASYNC16(sa + dA[it], srcA[it] + ko);
#pragma unroll
            for (int it = 0; it < 2; ++it) CP_ASYNC16(sbB + dB[it], srcB[it] + (size_t)ko * DIM);
        }
        CP_COMMIT();
    };

    load_chunk(0);
    load_chunk(1);
    load_chunk(2);

    int lrow = lane & 15, lcol = (lane >> 4) << 3;

    for (int j = 0; j < 64; ++j) {
        load_chunk(j + 3);
        CP_WAIT3();
        __syncthreads();
        uint32_t st = sb + (j % NSTAGE) * S2_STAGE;
        uint32_t sa = st, sbB = st + 128 * A_STRIDE;
#pragma unroll
        for (int ks = 0; ks < 2; ++ks) {
            uint32_t af[4][4];
#pragma unroll
            for (int mi = 0; mi < 4; ++mi) {
                uint32_t addr = sa + (wm * 64 + mi * 16 + lrow) * A_STRIDE + (ks * 16 + lcol) * 2;
                LDSM_X4(af[mi], addr);
            }
            uint32_t bf[2][4];
#pragma unroll
            for (int nh = 0; nh < 2; ++nh) {
                uint32_t col2 = (wn * 32 + nh * 16 + lcol) * 2;
                LDSM_X4_T(bf[nh], sbB + (ks * 16 + lrow) * B_STRIDE + col2);
            }
#pragma unroll
            for (int mi = 0; mi < 4; ++mi)
#pragma unroll
                for (int ni = 0; ni < 4; ++ni)
                    mma_f16(acc[mi][ni], af[mi], &bf[ni >> 1][(ni & 1) * 2]);
        }
    }

    int g = lane >> 2, tg = lane & 3;
#pragma unroll
    for (int mi = 0; mi < 4; ++mi)
#pragma unroll
        for (int rr = 0; rr < 2; ++rr) {
            int rg = m0 + wm * 64 + mi * 16 + g + rr * 8;
            if (rg < row_end) {
                int tok = g_tok[rg];
                float wgt = g_w[rg];
                float* yrow = y + (size_t)tok * DIM;
#pragma unroll
                for (int ni = 0; ni < 4; ++ni) {
                    int n = n0 + wn * 32 + ni * 8 + tg * 2;
                    float v0 = (acc[mi][ni][rr * 2]     + b2[e * DIM + n])     * wgt;
                    float v1 = (acc[mi][ni][rr * 2 + 1] + b2[e * DIM + n + 1]) * wgt;
                    atomicAdd(yrow + n, v0);
                    atomicAdd(yrow + n + 1, v1);
                }
            }
        }
}

// ---------------- launch ----------------
extern "C" void kernel_launch(void* const* d_in, const int* in_sizes, int n_in,
                              void* d_out, int out_size) {
    (void)in_sizes; (void)n_in; (void)out_size;
    const float* x  = (const float*)d_in[0];
    const float* Wg = (const float*)d_in[1];
    const float* bg = (const float*)d_in[2];
    const float* W1 = (const float*)d_in[3];
    const float* b1 = (const float*)d_in[4];
    const float* W2 = (const float*)d_in[5];
    const float* b2 = (const float*)d_in[6];
    const float* W3 = (const float*)d_in[7];
    const float* b3 = (const float*)d_in[8];
    float* y = (float*)d_out;

    const int G1_SMEM = 128 + NSTAGE * S1_STAGE;   // ~135 KB
    const int G2_SMEM = 128 + NSTAGE * S2_STAGE;   // ~93 KB
    cudaFuncSetAttribute(gemm1_hm, cudaFuncAttributeMaxDynamicSharedMemorySize, G1_SMEM);
    cudaFuncSetAttribute(gemm2_hm, cudaFuncAttributeMaxDynamicSharedMemorySize, G2_SMEM);

    init_kernel<<<1, 32>>>();
    gate_kernel<<<T_TOK, 256>>>(x, Wg, bg, (float4*)y);
    scan_kernel<<<1, 32>>>();
    scatter_kernel<<<NR / 256, 256>>>();

    size_t total_f4 = X4F + 3 * W4F;
    cvt_all_kernel<<<(unsigned)(total_f4 / 256), 256>>>(
        (const float4*)x, (const float4*)W1, (const float4*)W3, (const float4*)W2);

    gemm1_hm<<<dim3(INTER / 128, 144), 256, G1_SMEM>>>(b1, b3);
    gemm2_hm<<<dim3(DIM / 128, 144), 256, G2_SMEM>>>(b2, y);
}

// round 8
// speedup vs baseline: 3.3023x; 1.0354x over previous
#include <cuda_runtime.h>
#include <cuda_fp16.h>
#include <cstdint>

#define T_TOK 8192
#define DIM   1024
#define NE    16
#define INTER 2048
#define NR    (T_TOK * 2)
#define MAX_TILES 160

// ---------------- device scratch ----------------
__device__ int    g_topi[NR];
__device__ float  g_topw[NR];
__device__ int    g_cnt[NE];
__device__ int    g_off[NE + 1];
__device__ int    g_pos[NE];
__device__ int    g_tok[NR];
__device__ float  g_w[NR];
__device__ int    g_tm_e[MAX_TILES];
__device__ int    g_tm_m[MAX_TILES];
__device__ int    g_ntiles;
__device__ __half g_xh[(size_t)T_TOK * DIM];
__device__ __half g_W1h[(size_t)NE * DIM * INTER];   // [e][k][n] as in source
__device__ __half g_W3h[(size_t)NE * DIM * INTER];
__device__ __half g_W2h[(size_t)NE * INTER * DIM];
__device__ __half g_Hh[(size_t)(NR + 128) * INTER];  // zero-init; padding rows stay 0

#define X4F ((size_t)T_TOK * DIM / 4)            // 2,097,152 float4s in x
#define W4F ((size_t)NE * DIM * INTER / 4)       // 8,388,608 float4s per weight

// ---------------- helpers ----------------
__device__ __forceinline__ uint32_t smem_u32(const void* p) {
    uint32_t a;
    asm("{ .reg .u64 t; cvta.to.shared.u64 t, %1; cvt.u32.u64 %0, t; }" : "=r"(a) : "l"(p));
    return a;
}

__device__ __forceinline__ void mma_f16(float* c, const uint32_t* a, const uint32_t* b) {
    asm volatile(
        "mma.sync.aligned.m16n8k16.row.col.f32.f16.f16.f32 "
        "{%0,%1,%2,%3}, {%4,%5,%6,%7}, {%8,%9}, {%0,%1,%2,%3};\n"
        : "+f"(c[0]), "+f"(c[1]), "+f"(c[2]), "+f"(c[3])
        : "r"(a[0]), "r"(a[1]), "r"(a[2]), "r"(a[3]), "r"(b[0]), "r"(b[1]));
}

#define LDSM_X4(r, addr) \
    asm volatile("ldmatrix.sync.aligned.m8n8.x4.shared.b16 {%0,%1,%2,%3}, [%4];" \
        : "=r"((r)[0]), "=r"((r)[1]), "=r"((r)[2]), "=r"((r)[3]) : "r"(addr))
#define LDSM_X4_T(r, addr) \
    asm volatile("ldmatrix.sync.aligned.m8n8.x4.trans.shared.b16 {%0,%1,%2,%3}, [%4];" \
        : "=r"((r)[0]), "=r"((r)[1]), "=r"((r)[2]), "=r"((r)[3]) : "r"(addr))

#define CP_ASYNC16(dst, src) \
    asm volatile("cp.async.cg.shared.global [%0], [%1], 16;\n" :: "r"(dst), "l"(src) : "memory")
#define CP_COMMIT() asm volatile("cp.async.commit_group;\n" ::: "memory")
#define CP_WAIT3()  asm volatile("cp.async.wait_group 3;\n" ::: "memory")

// strides (bytes): A tile 128x32 fp16 rows padded 64->80B; B tile 32x128 fp16 rows 256->272B
#define A_STRIDE 80
#define B_STRIDE 272
#define S1_STAGE (128 * A_STRIDE + 2 * 32 * B_STRIDE)   // 27648
#define S2_STAGE (128 * A_STRIDE + 32 * B_STRIDE)        // 18944
#define NSTAGE 5

// ---------------- routing ----------------
__global__ void init_kernel() {
    int i = threadIdx.x;
    if (i < NE) g_cnt[i] = 0;
}

// blocks [0, T_TOK): gate + zero y row + convert own x row to fp16
// blocks [T_TOK, 2*T_TOK): convert W1 || W3 to fp16
__global__ void gate_cvt_kernel(const float* __restrict__ x,
                                const float* __restrict__ Wg,
                                const float* __restrict__ bg,
                                float4* __restrict__ y4,
                                const float4* __restrict__ W1f,
                                const float4* __restrict__ W3f) {
    int tid = threadIdx.x;
    if (blockIdx.x >= T_TOK) {
        // ---- W1/W3 conversion: 8192 blocks x 2048 float4 = 2*W4F ----
        size_t base = (size_t)(blockIdx.x - T_TOK) * 2048;
#pragma unroll
        for (int it = 0; it < 8; ++it) {
            size_t i = base + it * 256 + tid;
            const float4* src; __half2* dst; size_t o;
            if (i < W4F) { src = W1f; o = i;       dst = (__half2*)g_W1h; }
            else         { src = W3f; o = i - W4F; dst = (__half2*)g_W3h; }
            float4 v = src[o];
            dst[2 * o]     = __floats2half2_rn(v.x, v.y);
            dst[2 * o + 1] = __floats2half2_rn(v.z, v.w);
        }
        return;
    }

    int t = blockIdx.x;
    y4[(size_t)t * 256 + tid] = make_float4(0.f, 0.f, 0.f, 0.f);

    // convert this token's x row (re-read as float4; L1/L2 hot)
    {
        float4 v = ((const float4*)x)[(size_t)t * 256 + tid];
        __half2* dst = (__half2*)(g_xh + (size_t)t * DIM);
        dst[2 * tid]     = __floats2half2_rn(v.x, v.y);
        dst[2 * tid + 1] = __floats2half2_rn(v.z, v.w);
    }

    int e = tid & 15, c = tid >> 4;
    const float* xr = x + (size_t)t * DIM;
    float s = 0.f;
    int d0 = c * 64;
#pragma unroll 8
    for (int d = d0; d < d0 + 64; ++d) s += xr[d] * Wg[d * NE + e];
    __shared__ float part[256];
    __shared__ float logits[NE];
    part[tid] = s;
    __syncthreads();
    if (tid < NE) {
        float tot = bg[tid];
#pragma unroll
        for (int cc = 0; cc < 16; ++cc) tot += part[cc * 16 + tid];
        logits[tid] = tot;
    }
    __syncthreads();
    if (tid == 0) {
        int i0 = 0; float m0 = logits[0];
#pragma unroll
        for (int k = 1; k < NE; ++k)
            if (logits[k] > m0) { m0 = logits[k]; i0 = k; }
        int i1 = -1; float m1 = -3.4e38f;
#pragma unroll
        for (int k = 0; k < NE; ++k)
            if (k != i0 && logits[k] > m1) { m1 = logits[k]; i1 = k; }
        float e1 = expf(m1 - m0);
        float inv = 1.f / (1.f + e1);
        g_topi[t * 2]     = i0;  g_topw[t * 2]     = inv;
        g_topi[t * 2 + 1] = i1;  g_topw[t * 2 + 1] = e1 * inv;
        atomicAdd(&g_cnt[i0], 1);
        atomicAdd(&g_cnt[i1], 1);
    }
}

__global__ void scan_kernel() {
    if (threadIdx.x == 0 && blockIdx.x == 0) {
        int off = 0, nt = 0;
        for (int e = 0; e < NE; ++e) {
            g_off[e] = off; g_pos[e] = off;
            int ne = g_cnt[e];
            for (int j = 0; j < ne; j += 128) { g_tm_e[nt] = e; g_tm_m[nt] = off + j; ++nt; }
            off += ne;
        }
        g_off[NE] = off;
        g_ntiles  = nt;
    }
}

__global__ void scatter_kernel() {
    int i = blockIdx.x * 256 + threadIdx.x;
    if (i < NR) {
        int e = g_topi[i];
        int p = atomicAdd(&g_pos[e], 1);
        g_tok[p] = i >> 1;
        g_w[p]   = g_topw[i];
    }
}

// ---------------- GEMM1: H = silu(X@W1+b1) * (X@W3+b3)  [+ W2 cvt tail blocks] --
// block 128M x 128N x 32K, 8 warps (2M x 4N), warp tile 64x32, m16n8k16 fp16 MMA
// 5-stage cp.async pipeline, prefetch distance 3, single barrier per chunk.
// grid.y in [144, 400): convert a 2048-float4 slice of W2 instead (runs in tail).
__global__ __launch_bounds__(256, 1) void gemm1_hm(const float* __restrict__ b1,
                                                   const float* __restrict__ b3,
                                                   const float4* __restrict__ W2f) {
    if (blockIdx.y >= 144) {
        size_t base = ((size_t)(blockIdx.y - 144) * 16 + blockIdx.x) * 2048;
        __half2* dst = (__half2*)g_W2h;
#pragma unroll
        for (int it = 0; it < 8; ++it) {
            size_t i = base + it * 256 + threadIdx.x;
            float4 v = W2f[i];
            dst[2 * i]     = __floats2half2_rn(v.x, v.y);
            dst[2 * i + 1] = __floats2half2_rn(v.z, v.w);
        }
        return;
    }

    int t = blockIdx.y;
    if (t >= g_ntiles) return;
    int e = g_tm_e[t], m0 = g_tm_m[t], row_end = g_off[e + 1];
    int n0 = blockIdx.x * 128;
    int tid = threadIdx.x, lane = tid & 31, wid = tid >> 5;
    int wm = wid >> 2, wn = wid & 3;

    extern __shared__ char sm[];
    uint32_t sb = (smem_u32(sm) + 127) & ~127u;

    __shared__ int s_tok[128];
    if (tid < 128) {
        int rg = m0 + tid;
        s_tok[tid] = (rg < row_end) ? g_tok[rg] : 0;
    }
    __syncthreads();

    const __half* W1e = g_W1h + (size_t)e * DIM * INTER;
    const __half* W3e = g_W3h + (size_t)e * DIM * INTER;

    const __half* srcA[2]; const __half* srcB1[2]; const __half* srcB3[2];
    uint32_t dA[2], dB[2];
#pragma unroll
    for (int it = 0; it < 2; ++it) {
        int idx = tid + it * 256;
        int rowA = idx >> 2, kcA = idx & 3;
        srcA[it] = g_xh + (size_t)s_tok[rowA] * DIM + kcA * 8;
        dA[it]   = rowA * A_STRIDE + kcA * 16;
        int krB = idx >> 4, ncB = idx & 15;
        srcB1[it] = W1e + (size_t)krB * INTER + n0 + ncB * 8;
        srcB3[it] = W3e + (size_t)krB * INTER + n0 + ncB * 8;
        dB[it]    = krB * B_STRIDE + ncB * 16;
    }

    float acc1[4][4][4], acc3[4][4][4];
#pragma unroll
    for (int mi = 0; mi < 4; ++mi)
#pragma unroll
        for (int ni = 0; ni < 4; ++ni)
#pragma unroll
            for (int q = 0; q < 4; ++q) { acc1[mi][ni][q] = 0.f; acc3[mi][ni][q] = 0.f; }

    auto load_chunk = [&](int c) {
        if (c < 32) {
            uint32_t st = sb + (c % NSTAGE) * S1_STAGE;
            uint32_t sa = st, sb1 = st + 128 * A_STRIDE, sb3 = sb1 + 32 * B_STRIDE;
            int ko = c * 32;
#pragma unroll
            for (int it = 0; it < 2; ++it) CP_ASYNC16(sa + dA[it], srcA[it] + ko);
#pragma unroll
            for (int it = 0; it < 2; ++it) CP_ASYNC16(sb1 + dB[it], srcB1[it] + (size_t)ko * INTER);
#pragma unroll
            for (int it = 0; it < 2; ++it) CP_ASYNC16(sb3 + dB[it], srcB3[it] + (size_t)ko * INTER);
        }
        CP_COMMIT();
    };

    load_chunk(0);
    load_chunk(1);
    load_chunk(2);

    int lrow = lane & 15, lcol = (lane >> 4) << 3;

    for (int j = 0; j < 32; ++j) {
        load_chunk(j + 3);
        CP_WAIT3();            // chunk j resident (3 newer groups may be in flight)
        __syncthreads();       // single barrier per chunk
        uint32_t st = sb + (j % NSTAGE) * S1_STAGE;
        uint32_t sa = st, sb1 = st + 128 * A_STRIDE, sb3 = sb1 + 32 * B_STRIDE;
#pragma unroll
        for (int ks = 0; ks < 2; ++ks) {
            uint32_t af[4][4];
#pragma unroll
            for (int mi = 0; mi < 4; ++mi) {
                uint32_t addr = sa + (wm * 64 + mi * 16 + lrow) * A_STRIDE + (ks * 16 + lcol) * 2;
                LDSM_X4(af[mi], addr);
            }
            uint32_t bf1[2][4], bf3[2][4];
#pragma unroll
            for (int nh = 0; nh < 2; ++nh) {
                uint32_t col2 = (wn * 32 + nh * 16 + lcol) * 2;
                uint32_t rowo = (ks * 16 + lrow) * B_STRIDE;
                LDSM_X4_T(bf1[nh], sb1 + rowo + col2);
                LDSM_X4_T(bf3[nh], sb3 + rowo + col2);
            }
#pragma unroll
            for (int mi = 0; mi < 4; ++mi)
#pragma unroll
                for (int ni = 0; ni < 4; ++ni) {
                    mma_f16(acc1[mi][ni], af[mi], &bf1[ni >> 1][(ni & 1) * 2]);
                    mma_f16(acc3[mi][ni], af[mi], &bf3[ni >> 1][(ni & 1) * 2]);
                }
        }
    }

    // epilogue: silu(h1+b1)*(h3+b3) -> g_Hh (fp16)
    int g = lane >> 2, tg = lane & 3;
#pragma unroll
    for (int mi = 0; mi < 4; ++mi)
#pragma unroll
        for (int rr = 0; rr < 2; ++rr) {
            int rg = m0 + wm * 64 + mi * 16 + g + rr * 8;
            if (rg < row_end) {
                size_t hrow = (size_t)rg * INTER;
#pragma unroll
                for (int ni = 0; ni < 4; ++ni) {
                    int n = n0 + wn * 32 + ni * 8 + tg * 2;
                    float a0 = acc1[mi][ni][rr * 2]     + b1[e * INTER + n];
                    float a1 = acc1[mi][ni][rr * 2 + 1] + b1[e * INTER + n + 1];
                    float g0 = a0 / (1.f + __expf(-a0));
                    float g1 = a1 / (1.f + __expf(-a1));
                    float h0 = g0 * (acc3[mi][ni][rr * 2]     + b3[e * INTER + n]);
                    float h1 = g1 * (acc3[mi][ni][rr * 2 + 1] + b3[e * INTER + n + 1]);
                    *(__half2*)(g_Hh + hrow + n) = __floats2half2_rn(h0, h1);
                }
            }
        }
}

// ---------------- GEMM2: y += (H @ W2 + b2) * w ----------------
__global__ __launch_bounds__(256, 2) void gemm2_hm(const float* __restrict__ b2,
                                                   float* __restrict__ y) {
    int t = blockIdx.y;
    if (t >= g_ntiles) return;
    int e = g_tm_e[t], m0 = g_tm_m[t], row_end = g_off[e + 1];
    int n0 = blockIdx.x * 128;
    int tid = threadIdx.x, lane = tid & 31, wid = tid >> 5;
    int wm = wid >> 2, wn = wid & 3;

    extern __shared__ char sm[];
    uint32_t sb = (smem_u32(sm) + 127) & ~127u;

    const __half* W2e = g_W2h + (size_t)e * INTER * DIM;

    const __half* srcA[2]; const __half* srcB[2];
    uint32_t dA[2], dB[2];
#pragma unroll
    for (int it = 0; it < 2; ++it) {
        int idx = tid + it * 256;
        int rowA = idx >> 2, kcA = idx & 3;
        srcA[it] = g_Hh + (size_t)(m0 + rowA) * INTER + kcA * 8;
        dA[it]   = rowA * A_STRIDE + kcA * 16;
        int krB = idx >> 4, ncB = idx & 15;
        srcB[it] = W2e + (size_t)krB * DIM + n0 + ncB * 8;
        dB[it]   = krB * B_STRIDE + ncB * 16;
    }

    float acc[4][4][4];
#pragma unroll
    for (int mi = 0; mi < 4; ++mi)
#pragma unroll
        for (int ni = 0; ni < 4; ++ni)
#pragma unroll
            for (int q = 0; q < 4; ++q) acc[mi][ni][q] = 0.f;

    auto load_chunk = [&](int c) {
        if (c < 64) {
            uint32_t st = sb + (c % NSTAGE) * S2_STAGE;
            uint32_t sa = st, sbB = st + 128 * A_STRIDE;
            int ko = c * 32;
#pragma unroll
            for (int it = 0; it < 2; ++it) CP_ASYNC16(sa + dA[it], srcA[it] + ko);
#pragma unroll
            for (int it = 0; it < 2; ++it) CP_ASYNC16(sbB + dB[it], srcB[it] + (size_t)ko * DIM);
        }
        CP_COMMIT();
    };

    load_chunk(0);
    load_chunk(1);
    load_chunk(2);

    int lrow = lane & 15, lcol = (lane >> 4) << 3;

    for (int j = 0; j < 64; ++j) {
        load_chunk(j + 3);
        CP_WAIT3();
        __syncthreads();
        uint32_t st = sb + (j % NSTAGE) * S2_STAGE;
        uint32_t sa = st, sbB = st + 128 * A_STRIDE;
#pragma unroll
        for (int ks = 0; ks < 2; ++ks) {
            uint32_t af[4][4];
#pragma unroll
            for (int mi = 0; mi < 4; ++mi) {
                uint32_t addr = sa + (wm * 64 + mi * 16 + lrow) * A_STRIDE + (ks * 16 + lcol) * 2;
                LDSM_X4(af[mi], addr);
            }
            uint32_t bf[2][4];
#pragma unroll
            for (int nh = 0; nh < 2; ++nh) {
                uint32_t col2 = (wn * 32 + nh * 16 + lcol) * 2;
                LDSM_X4_T(bf[nh], sbB + (ks * 16 + lrow) * B_STRIDE + col2);
            }
#pragma unroll
            for (int mi = 0; mi < 4; ++mi)
#pragma unroll
                for (int ni = 0; ni < 4; ++ni)
                    mma_f16(acc[mi][ni], af[mi], &bf[ni >> 1][(ni & 1) * 2]);
        }
    }

    int g = lane >> 2, tg = lane & 3;
#pragma unroll
    for (int mi = 0; mi < 4; ++mi)
#pragma unroll
        for (int rr = 0; rr < 2; ++rr) {
            int rg = m0 + wm * 64 + mi * 16 + g + rr * 8;
            if (rg < row_end) {
                int tok = g_tok[rg];
                float wgt = g_w[rg];
                float* yrow = y + (size_t)tok * DIM;
#pragma unroll
                for (int ni = 0; ni < 4; ++ni) {
                    int n = n0 + wn * 32 + ni * 8 + tg * 2;
                    float v0 = (acc[mi][ni][rr * 2]     + b2[e * DIM + n])     * wgt;
                    float v1 = (acc[mi][ni][rr * 2 + 1] + b2[e * DIM + n + 1]) * wgt;
                    atomicAdd(yrow + n, v0);
                    atomicAdd(yrow + n + 1, v1);
                }
            }
        }
}

// ---------------- launch ----------------
extern "C" void kernel_launch(void* const* d_in, const int* in_sizes, int n_in,
                              void* d_out, int out_size) {
    (void)in_sizes; (void)n_in; (void)out_size;
    const float* x  = (const float*)d_in[0];
    const float* Wg = (const float*)d_in[1];
    const float* bg = (const float*)d_in[2];
    const float* W1 = (const float*)d_in[3];
    const float* b1 = (const float*)d_in[4];
    const float* W2 = (const float*)d_in[5];
    const float* b2 = (const float*)d_in[6];
    const float* W3 = (const float*)d_in[7];
    const float* b3 = (const float*)d_in[8];
    float* y = (float*)d_out;

    const int G1_SMEM = 128 + NSTAGE * S1_STAGE;   // ~135 KB
    const int G2_SMEM = 128 + NSTAGE * S2_STAGE;   // ~93 KB
    cudaFuncSetAttribute(gemm1_hm, cudaFuncAttributeMaxDynamicSharedMemorySize, G1_SMEM);
    cudaFuncSetAttribute(gemm2_hm, cudaFuncAttributeMaxDynamicSharedMemorySize, G2_SMEM);

    init_kernel<<<1, 32>>>();
    // gate (8192 blocks) + W1/W3 fp16 conversion (8192 blocks) in one grid
    gate_cvt_kernel<<<2 * T_TOK, 256>>>(x, Wg, bg, (float4*)y,
                                        (const float4*)W1, (const float4*)W3);
    scan_kernel<<<1, 32>>>();
    scatter_kernel<<<NR / 256, 256>>>();

    // gemm1 tiles (y<144) + W2 conversion (y in [144,400)) in one grid
    gemm1_hm<<<dim3(INTER / 128, 144 + 256), 256, G1_SMEM>>>(b1, b3, (const float4*)W2);
    gemm2_hm<<<dim3(DIM / 128, 144), 256, G2_SMEM>>>(b2, y);
}